// round 11
// baseline (speedup 1.0000x reference)
#include <cuda_runtime.h>
#include <cuda_fp16.h>
#include <cstdint>

// ---------------------------------------------------------------------------
// x_{k+1}[v] = relu( sum_d W[v,d]*x_k[src[v,d]] - demand[v] ), 32 iters,
// out = weights * x_32.  B=4, N=100K, D=16 (12 valid).
//
// R11 = R10 + TMA MULTICAST staging: grid=128 as 16 clusters of 8 CTAs,
// cluster-aligned per batch (32 blocks/batch). Each CTA bulk-loads a 1/8
// slice of the batch x and multicasts it to all 8 cluster CTAs; every CTA's
// mbarrier expects the full N*2 bytes. L2 staging traffic /4-8. Host guards
// residency via cudaOccupancyMaxActiveClusters; falls back to plain R10
// launch (kernel auto-detects csz==1).
// ---------------------------------------------------------------------------

#define MAXN       430000
#define MAXSLOT    16
#define MAXQUAD    4
#define TPB        1024
#define DPT        4
#define SMEM_BYTES 200704
#define MAXIT      33
#define MAXB       16
#define CSZ        8

__device__ float g_w[(size_t)MAXN * MAXSLOT];     // exact softmax weights (epilogue)
__device__ uint4 g_eq[(size_t)2 * MAXQUAD * MAXN];// packed/wide edge quads
__device__ int   g_maxcnt;
__device__ unsigned g_ctr[MAXIT * MAXB * 32];     // 128B-strided counters
__device__ __align__(16) __half g_xa[MAXN];
__device__ __align__(16) __half g_xb[MAXN];

__device__ __forceinline__ unsigned smem_u32(const void* p) {
    unsigned r;
    asm("{ .reg .u64 t; cvta.to.shared.u64 t, %1; cvt.u32.u64 %0, t; }"
        : "=r"(r) : "l"(p));
    return r;
}

__device__ __forceinline__ void mbar_wait(unsigned mb, unsigned parity) {
    unsigned done;
    do {
        asm volatile("{ .reg .pred p; "
                     "mbarrier.try_wait.parity.acquire.cta.shared::cta.b64 p, [%1], %2, 0x989680; "
                     "selp.b32 %0, 1, 0, p; }"
                     : "=r"(done) : "r"(mb), "r"(parity) : "memory");
    } while (!done);
}

__device__ __forceinline__ unsigned ld_acq(const unsigned* p) {
    unsigned v;
    asm volatile("ld.acquire.gpu.u32 %0, [%1];" : "=r"(v) : "l"(p) : "memory");
    return v;
}

__device__ __forceinline__ void bar_sync(unsigned* ctr, unsigned expect) {
    __threadfence();
    __syncthreads();
    if (threadIdx.x == 0) {
        asm volatile("fence.proxy.async;" ::: "memory");
        atomicAdd(ctr, 1u);
        while (ld_acq(ctr) < expect) { }
    }
    __syncthreads();
}

// --- everything in one persistent kernel ------------------------------------
__global__ void __launch_bounds__(TPB, 1) k_all(const float* __restrict__ fp,
                                                const int*   __restrict__ adj,
                                                const float* __restrict__ dem,
                                                float*       __restrict__ out,
                                                int BN, int D, int niter,
                                                const int* __restrict__ num_nodes) {
    extern __shared__ unsigned char xs[];
    __shared__ __align__(8) unsigned long long mbar;

    const int N    = __ldg(num_nodes);
    const int B    = BN / N;
    const int bpb  = gridDim.x / B;
    const unsigned nblk = (unsigned)(bpb * B);
    const int blk  = blockIdx.x;
    if (blk >= (int)nblk) return;
    const int b     = blk / bpb;
    const int ib    = blk - b * bpb;
    const int spb   = (N + bpb - 1) / bpb;
    const int start = b * N + ib * spb;
    const int stop  = min(start + spb, (b + 1) * N);

    const unsigned bytes = (unsigned)N * 2u;
    const bool whole   = (bytes <= SMEM_BYTES);
    const bool bulk_ok = whole && ((bytes & 15u) == 0u);

    // cluster geometry (1,0 when launched without clusters)
    unsigned csz, crank;
    asm("mov.u32 %0, %%cluster_nctaid.x;" : "=r"(csz));
    asm("mov.u32 %0, %%cluster_ctarank;"  : "=r"(crank));
    const bool mc = bulk_ok && (csz > 1) && ((unsigned)bpb % csz == 0u);

    const int grp = (B <= MAXB) ? b : 0;
    const unsigned expect = (B <= MAXB) ? (unsigned)bpb : nblk;

    const unsigned mb = smem_u32(&mbar);
    if (threadIdx.x == 0)
        asm volatile("mbarrier.init.shared.b64 [%0], %1;" :: "r"(mb), "r"(1) : "memory");

    // ======================= PHASE A: prep =================================
    {
        const int gstride = (int)nblk * TPB;
        int maxd = 0;
        unsigned* e1 = (unsigned*)g_eq;

        for (int t = blk * TPB + threadIdx.x; t < BN; t += gstride) {
            const int bb   = t / N;
            const int base = bb * N;
            const int u    = t - base;

            float e[MAXSLOT];
            int   a[MAXSLOT];
            float sum = 0.f;
            if (D == MAXSLOT) {
                const float4* f4 = (const float4*)(fp + (size_t)t * MAXSLOT);
                const int4*   a4 = (const int4*)(adj + (size_t)t * MAXSLOT);
#pragma unroll
                for (int g = 0; g < 4; ++g) {
                    float4 f = __ldg(f4 + g);
                    int4   av = __ldg(a4 + g);
                    a[4*g+0] = av.x; a[4*g+1] = av.y; a[4*g+2] = av.z; a[4*g+3] = av.w;
                    e[4*g+0] = (av.x == N) ? 0.f : __expf(f.x);
                    e[4*g+1] = (av.y == N) ? 0.f : __expf(f.y);
                    e[4*g+2] = (av.z == N) ? 0.f : __expf(f.z);
                    e[4*g+3] = (av.w == N) ? 0.f : __expf(f.w);
                    sum += e[4*g+0] + e[4*g+1] + e[4*g+2] + e[4*g+3];
                }
            } else {
                for (int d = 0; d < D; ++d) {
                    a[d] = __ldg(adj + (size_t)t * D + d);
                    float f = __ldg(fp + (size_t)t * D + d);
                    e[d] = (a[d] == N) ? 0.f : __expf(f);
                    sum += e[d];
                }
            }
            const float inv = 1.f / sum;

            if (D == MAXSLOT) {
                float4* w4 = (float4*)(g_w + (size_t)t * MAXSLOT);
#pragma unroll
                for (int g = 0; g < 4; ++g)
                    w4[g] = make_float4(e[4*g+0]*inv, e[4*g+1]*inv,
                                        e[4*g+2]*inv, e[4*g+3]*inv);
            } else {
                for (int d = 0; d < D; ++d)
                    g_w[(size_t)t * D + d] = e[d] * inv;
            }

            for (int d = 0; d < D; ++d) {
                if (a[d] != N) {
                    const int v = base + a[d];
                    const int q = d >> 2;
                    const float w = e[d] * inv;
                    const size_t lane = (((size_t)q * BN + v) << 2) + (d & 3);
                    if (whole) {
                        unsigned wq = (unsigned)(w * 32767.f + 0.5f);
                        if (wq > 32767u) wq = 32767u;
                        e1[lane] = (unsigned)u | (wq << 17);
                    } else {
                        e1[lane] = (unsigned)u;
                        e1[(((size_t)(MAXQUAD + q) * BN + v) << 2) + (d & 3)] =
                            __float_as_uint(w);
                    }
                    maxd = max(maxd, d + 1);
                }
            }
        }
        maxd = __reduce_max_sync(0xffffffffu, maxd);
        if ((threadIdx.x & 31) == 0 && maxd > 0) atomicMax(&g_maxcnt, maxd);
    }

    bar_sync(&g_ctr[(MAXIT - 1) * MAXB * 32], nblk);   // global prep barrier

    const int Q = (*(volatile int*)&g_maxcnt + 3) >> 2;

    float dm[DPT];
    int   dl[DPT];
    int   kmax = 0;
#pragma unroll
    for (int k = 0; k < DPT; ++k) {
        int d = start + threadIdx.x + k * TPB;
        dl[k] = min(d, stop - 1);
        dm[k] = (d < stop) ? __ldg(dem + d) : 0.f;
        if (start + k * TPB < stop) kmax = k + 1;
    }

    const __half* xh = (const __half*)xs;
    const float INV15 = 1.0f / 32767.0f;
    const unsigned ss = (((bytes + csz - 1) / csz) + 15u) & ~15u;   // slice bytes
    const unsigned short mcmask = (unsigned short)((1u << csz) - 1u);

    // ======================= PHASE B: iterations ============================
    for (int it = 0; it < niter; ++it) {
        float r_out[DPT];

        if (it == 0) {
#pragma unroll
            for (int k = 0; k < DPT; ++k) r_out[k] = fmaxf(-dm[k], 0.f);
        } else {
            const __half* xo = (it & 1) ? g_xb : g_xa;

            if (bulk_ok && threadIdx.x == 0) {
                asm volatile("mbarrier.arrive.expect_tx.shared.b64 _, [%0], %1;"
                             :: "r"(mb), "r"(bytes) : "memory");
                if (mc) {
                    // cooperative slice: this CTA loads slice[crank], multicast to cluster
                    const unsigned off = crank * ss;
                    if (off < bytes) {
                        const unsigned sz = min(bytes - off, ss);
                        asm volatile(
                            "cp.async.bulk.shared::cluster.global.mbarrier::complete_tx::bytes"
                            ".multicast::cluster [%0], [%1], %2, [%3], %4;"
                            :: "r"(smem_u32(xs) + off),
                               "l"((const char*)(xo + (size_t)b * N) + off),
                               "r"(sz), "r"(mb), "h"(mcmask)
                            : "memory");
                    }
                } else {
                    asm volatile("cp.async.bulk.shared::cta.global.mbarrier::complete_tx::bytes "
                                 "[%0], [%1], %2, [%3];"
                                 :: "r"(smem_u32(xs)), "l"(xo + (size_t)b * N),
                                    "r"(bytes), "r"(mb)
                                 : "memory");
                }
            }

            if (whole) {
                uint4 e0[DPT];
#pragma unroll
                for (int k = 0; k < DPT; ++k) {
                    if (k >= kmax) break;
                    e0[k] = __ldcg(&g_eq[dl[k]]);
                }

                if (!bulk_ok) {
                    __half* dh = (__half*)xs;
                    for (int i = threadIdx.x; i < N; i += TPB)
                        dh[i] = __ldcg(xo + (size_t)b * N + i);
                    __syncthreads();
                } else {
                    mbar_wait(mb, (unsigned)((it + 1) & 1));
                }

#pragma unroll
                for (int k = 0; k < DPT; ++k) {
                    if (k >= kmax) { r_out[k] = 0.f; continue; }
                    const uint4* ep = g_eq + dl[k];
                    float a = 0.f;
                    uint4 e = e0[k];
#pragma unroll 3
                    for (int q = 1; q < Q; ++q) {
                        uint4 f = __ldcg(ep + (size_t)q * BN);
                        a = fmaf(__uint2float_rn(e.x >> 17), __half2float(xh[e.x & 0x1FFFFu]), a);
                        a = fmaf(__uint2float_rn(e.y >> 17), __half2float(xh[e.y & 0x1FFFFu]), a);
                        a = fmaf(__uint2float_rn(e.z >> 17), __half2float(xh[e.z & 0x1FFFFu]), a);
                        a = fmaf(__uint2float_rn(e.w >> 17), __half2float(xh[e.w & 0x1FFFFu]), a);
                        e = f;
                    }
                    a = fmaf(__uint2float_rn(e.x >> 17), __half2float(xh[e.x & 0x1FFFFu]), a);
                    a = fmaf(__uint2float_rn(e.y >> 17), __half2float(xh[e.y & 0x1FFFFu]), a);
                    a = fmaf(__uint2float_rn(e.z >> 17), __half2float(xh[e.z & 0x1FFFFu]), a);
                    a = fmaf(__uint2float_rn(e.w >> 17), __half2float(xh[e.w & 0x1FFFFu]), a);
                    r_out[k] = fmaxf(fmaf(a, INV15, -dm[k]), 0.f);
                }
            } else {
                const __half* xob = xo + (size_t)b * N;
#pragma unroll
                for (int k = 0; k < DPT; ++k) {
                    if (k >= kmax) { r_out[k] = 0.f; continue; }
                    const uint4* ep = g_eq + dl[k];
                    float a = 0.f;
                    for (int q = 0; q < Q; ++q) {
                        uint4 fs = __ldcg(ep + (size_t)q * BN);
                        uint4 wb = __ldcg(ep + (size_t)(MAXQUAD + q) * BN);
                        a = fmaf(__uint_as_float(wb.x), __half2float(__ldcg(xob + fs.x)), a);
                        a = fmaf(__uint_as_float(wb.y), __half2float(__ldcg(xob + fs.y)), a);
                        a = fmaf(__uint_as_float(wb.z), __half2float(__ldcg(xob + fs.z)), a);
                        a = fmaf(__uint_as_float(wb.w), __half2float(__ldcg(xob + fs.w)), a);
                    }
                    r_out[k] = fmaxf(a - dm[k], 0.f);
                }
            }
        }

        if (it == niter - 1) {
            __syncthreads();
            float* rs = (float*)xs;
#pragma unroll
            for (int k = 0; k < DPT; ++k) {
                int d = start + threadIdx.x + k * TPB;
                if (d < stop) rs[d - start] = r_out[k];
            }
            __syncthreads();
            const int rows = stop - start;
            if ((D & 3) == 0) {
                const int dq = D >> 2;
                const int total4 = rows * dq;
                const float4* w4 = (const float4*)(g_w + (size_t)start * D);
                float4*       o4 = (float4*)(out + (size_t)start * D);
                for (int i = threadIdx.x; i < total4; i += TPB) {
                    float4 w = __ldcg(w4 + i);
                    float  r = rs[i / dq];
                    o4[i] = make_float4(w.x * r, w.y * r, w.z * r, w.w * r);
                }
            } else {
                const int total = rows * D;
                for (int i = threadIdx.x; i < total; i += TPB)
                    out[(size_t)start * D + i] = g_w[(size_t)start * D + i] * rs[i / D];
            }
        } else {
            __half* xn = (it & 1) ? g_xa : g_xb;
#pragma unroll
            for (int k = 0; k < DPT; ++k) {
                int d = start + threadIdx.x + k * TPB;
                if (d < stop) xn[d] = __float2half_rn(r_out[k]);
            }
            bar_sync(&g_ctr[(it * MAXB + grp) * 32], expect);
        }
    }
}

extern "C" void kernel_launch(void* const* d_in, const int* in_sizes, int n_in,
                              void* d_out, int out_size) {
    const float* fp  = (const float*)d_in[0];
    const float* dem = (const float*)d_in[1];
    const int*   adj = (const int*)d_in[2];
    const int*   nn  = (const int*)d_in[4];

    const int E  = in_sizes[0];
    const int BN = in_sizes[1];
    const int D  = E / BN;
    const int NITER = 32;

    void *pe, *pmc, *pct;
    cudaGetSymbolAddress(&pe, g_eq);
    cudaGetSymbolAddress(&pmc, g_maxcnt);
    cudaGetSymbolAddress(&pct, g_ctr);

    int sm = 148;
    cudaDeviceGetAttribute(&sm, cudaDevAttrMultiProcessorCount, 0);

    cudaFuncSetAttribute(k_all, cudaFuncAttributeMaxDynamicSharedMemorySize,
                         SMEM_BYTES);

    const size_t ebytes = (size_t)2 * MAXQUAD * BN * sizeof(uint4);
    cudaMemsetAsync(pe, 0, ebytes, 0);
    cudaMemsetAsync(pmc, 0, sizeof(int), 0);
    cudaMemsetAsync(pct, 0, sizeof(unsigned) * MAXIT * MAXB * 32, 0);

    // --- try clustered launch: grid = 16 clusters x 8 CTAs = 128 ------------
    const int gmc = (sm / CSZ) * CSZ >= 128 ? 128 : (sm / CSZ) * CSZ;
    bool launched = false;
    if (gmc >= CSZ) {
        cudaLaunchConfig_t cfg = {};
        cfg.gridDim  = dim3((unsigned)gmc, 1, 1);
        cfg.blockDim = dim3(TPB, 1, 1);
        cfg.dynamicSmemBytes = SMEM_BYTES;
        cudaLaunchAttribute attr[1];
        attr[0].id = cudaLaunchAttributeClusterDimension;
        attr[0].val.clusterDim.x = CSZ;
        attr[0].val.clusterDim.y = 1;
        attr[0].val.clusterDim.z = 1;
        cfg.attrs = attr;
        cfg.numAttrs = 1;

        int maxClusters = 0;
        cudaError_t qerr = cudaOccupancyMaxActiveClusters(&maxClusters, k_all, &cfg);
        if (qerr == cudaSuccess && maxClusters >= gmc / CSZ) {
            cudaError_t lerr = cudaLaunchKernelEx(&cfg, k_all,
                                                  fp, adj, dem, (float*)d_out,
                                                  BN, D, NITER, nn);
            launched = (lerr == cudaSuccess);
        } else {
            cudaGetLastError();   // clear any sticky query error
        }
    }
    if (!launched) {
        // plain persistent launch (kernel sees csz==1 -> solo staging path)
        k_all<<<sm, TPB, SMEM_BYTES>>>(fp, adj, dem, (float*)d_out, BN, D, NITER, nn);
    }
}